// round 16
// baseline (speedup 1.0000x reference)
#include <cuda_runtime.h>
#include <cuda_bf16.h>
#include <mma.h>
#include <math.h>
#include <cstdint>

using namespace nvcuda;

// ---------------- problem constants ----------------
#define NN 50000      // nodes
#define NB 128        // graphs / batch
#define NH 10         // heads
#define FD 78         // per-head feature
#define CC 780        // NH*FD
#define E0MAX 150000
#define EMAX  (E0MAX + NN)   // edges incl self loops
#define KP1 96               // GEMM1 K (78) padded to mult of 32
#define KP2 800              // GEMM2 K (780) padded to mult of 32
#define NP  896              // N padded (7*128) for B tiles
#define NBLK 49              // ceil(NN/1024)

// ---------------- scratch (device globals; no allocs) ----------------
__device__ float g_bufA[NN * CC];   // h = x@W_gat, later hg = relu(gat)@W_gcn
__device__ float g_bufB[NN * CC];   // relu(gcn_out)
__device__ __nv_bfloat16 g_Ah[NN * KP2];
__device__ __nv_bfloat16 g_Al[NN * KP2];
__device__ __nv_bfloat16 g_Bh1[KP1 * NP];   // GEMM1 B
__device__ __nv_bfloat16 g_Bl1[KP1 * NP];
__device__ __nv_bfloat16 g_Bh2[KP2 * NP];   // GEMM2 B
__device__ __nv_bfloat16 g_Bl2[KP2 * NP];
__device__ float g_wproj[FD * 20];  // [78][20]: cols 0..9 = W@att_src per head, 10..19 = W@att_dst
__device__ float g_asd[NN * 20];    // [n][20]: as (0..9), ad (10..19)
__device__ float g_m[NN * NH];
__device__ float g_inv[NN * NH];
__device__ int   g_degi[NN];
__device__ int   g_off[NN + 1];
__device__ int   g_cur[NN];
__device__ int   g_srccsr[EMAX];
__device__ float g_dinv[NN];
__device__ int   g_bstart[NB + 1];
__device__ int   g_bsum[64];
__device__ int   g_bsum2[64];
__device__ float g_g[NB * 1560];
__device__ float g_t1[NB * 1500];
__device__ float g_xc[NB * 384];
__device__ float g_xt2c[NB * 3872];
__device__ float g_xt1c[NB * 544];
__device__ float g_f1[NB * 1024];
__device__ float g_f2[NB * 512];

// ---------------- helpers ----------------
__device__ __forceinline__ void edge_sd(const int* ei, int E0, int e, int& s, int& d) {
    if (e < E0) { s = ei[e]; d = ei[E0 + e]; }
    else        { s = e - E0; d = e - E0; }
}

__device__ __forceinline__ void cp_async16(unsigned int smem, const void* gmem, int srcbytes) {
    asm volatile("cp.async.cg.shared.global [%0], [%1], 16, %2;\n"
                 :: "r"(smem), "l"(gmem), "r"(srcbytes));
}
__device__ __forceinline__ unsigned int smem_u32(const void* p) {
    return (unsigned int)__cvta_generic_to_shared(p);
}

// ---------------- CSR build ----------------
__global__ void k_zero_deg() {
    int i = blockIdx.x * blockDim.x + threadIdx.x;
    if (i < NN) g_degi[i] = 0;
}

__global__ void k_count(const int* __restrict__ ei, int E0, int E) {
    int e = blockIdx.x * blockDim.x + threadIdx.x;
    if (e >= E) return;
    int s, d; edge_sd(ei, E0, e, s, d);
    (void)s;
    atomicAdd(&g_degi[d], 1);
}

__global__ void k_scan1() {
    __shared__ int sh[1024];
    int tid = threadIdx.x;
    int i = blockIdx.x * 1024 + tid;
    int v = (i < NN) ? g_degi[i] : 0;
    sh[tid] = v;
    __syncthreads();
    #pragma unroll
    for (int o = 1; o < 1024; o <<= 1) {
        int t = (tid >= o) ? sh[tid - o] : 0;
        __syncthreads();
        sh[tid] += t;
        __syncthreads();
    }
    if (i < NN) g_off[i] = sh[tid] - v;      // block-local exclusive
    if (tid == 1023) g_bsum[blockIdx.x] = sh[1023];
}

__global__ void k_scan2() {
    __shared__ int sh[64];
    int t = threadIdx.x;
    int v = (t < NBLK) ? g_bsum[t] : 0;
    sh[t] = v;
    __syncthreads();
    #pragma unroll
    for (int o = 1; o < 64; o <<= 1) {
        int x = (t >= o) ? sh[t - o] : 0;
        __syncthreads();
        sh[t] += x;
        __syncthreads();
    }
    if (t < NBLK) g_bsum2[t] = sh[t] - v;    // exclusive
    if (t == 63) g_off[NN] = sh[63];         // total
}

// fused: finalize offsets + init cursors + dinv
__global__ void k_scan3() {
    int i = blockIdx.x * blockDim.x + threadIdx.x;
    if (i >= NN) return;
    int off = g_off[i] + g_bsum2[i >> 10];
    g_off[i] = off;
    g_cur[i] = off;
    float dg = (float)g_degi[i];
    g_dinv[i] = (dg > 0.f) ? rsqrtf(dg) : 0.f;
}

__global__ void k_fillcsr(const int* __restrict__ ei, int E0, int E) {
    int e = blockIdx.x * blockDim.x + threadIdx.x;
    if (e >= E) return;
    int s, d; edge_sd(ei, E0, e, s, d);
    int pos = atomicAdd(&g_cur[d], 1);
    g_srccsr[pos] = s;
}

__global__ void k_bstart(const int* __restrict__ batch) {
    int n = blockIdx.x * blockDim.x + threadIdx.x;
    if (n >= NN) return;
    int bn = batch[n];
    int bp = (n == 0) ? -1 : batch[n - 1];
    for (int g = bp + 1; g <= bn; g++) g_bstart[g] = n;
    if (n == NN - 1)
        for (int g = bn + 1; g <= NB; g++) g_bstart[g] = NN;
}

// ---------------- projected attention weights: wproj = W_gat (per-head) @ att ----------------
__global__ void k_wproj(const float* __restrict__ W, const float* __restrict__ att_src,
                        const float* __restrict__ att_dst) {
    int t = blockIdx.x * blockDim.x + threadIdx.x;
    if (t >= FD * 20) return;
    int i = t / 20, j = t % 20;
    int h = j % NH;
    const float* att = (j >= NH) ? att_dst : att_src;
    float s = 0.f;
    #pragma unroll 6
    for (int f = 0; f < FD; f++) s += W[(size_t)i * CC + h * FD + f] * att[h * FD + f];
    g_wproj[i * 20 + j] = s;
}

// ---------------- GAT softmax pass1: per-node online softmax over incident edges ----------------
__global__ __launch_bounds__(256)
void k_gat_pass1() {
    int w = (blockIdx.x * blockDim.x + threadIdx.x) >> 5;
    if (w >= NN) return;
    int lane = threadIdx.x & 31;
    int beg = g_off[w], end = g_off[w + 1];
    float ad = (lane < NH) ? g_asd[w * 20 + 10 + lane] : 0.f;
    float m = -1e30f, ssum = 0.f;
    for (int j = beg; j < end; j++) {
        int s = g_srccsr[j];
        if (lane < NH) {
            float e = g_asd[s * 20 + lane] + ad;
            e = (e > 0.f) ? e : 0.2f * e;
            float mn = fmaxf(m, e);
            ssum = ssum * expf(m - mn) + expf(e - mn);
            m = mn;
        }
    }
    if (lane < NH) {
        g_m[w * NH + lane] = m;
        g_inv[w * NH + lane] = 1.f / (ssum + 1e-16f);
    }
}

// ---------------- split-bf16 conversion ----------------
template<bool RELU>
__global__ void k_convA(const float* __restrict__ src, int M, int K, int Kp,
                        __nv_bfloat16* __restrict__ Ah, __nv_bfloat16* __restrict__ Al)
{
    size_t idx = (size_t)blockIdx.x * blockDim.x + threadIdx.x;
    if (idx >= (size_t)M * Kp) return;
    int c = (int)(idx % Kp);
    int r = (int)(idx / Kp);
    float v = 0.f;
    if (c < K) {
        v = src[(size_t)r * K + c];
        if (RELU) v = fmaxf(v, 0.f);
    }
    __nv_bfloat16 h = __float2bfloat16(v);
    Ah[idx] = h;
    Al[idx] = __float2bfloat16(v - __bfloat162float(h));
}

// B stored [k][NP] row-major, zero-padded columns/rows
__global__ void k_convB(const float* __restrict__ W, int K, int N, int Kp,
                        __nv_bfloat16* __restrict__ Bh, __nv_bfloat16* __restrict__ Bl)
{
    size_t idx = (size_t)blockIdx.x * blockDim.x + threadIdx.x;
    if (idx >= (size_t)Kp * NP) return;
    int n = (int)(idx % NP);
    int k = (int)(idx / NP);
    float v = (k < K && n < N) ? W[(size_t)k * N + n] : 0.f;
    __nv_bfloat16 h = __float2bfloat16(v);
    Bh[idx] = h;
    Bl[idx] = __float2bfloat16(v - __bfloat162float(h));
}

// ---------------- split-bf16 wmma GEMM v3 (BK=32, 2-stage, dynamic smem) ----------------
#define ALD 40      // A smem row stride (elems): 80B rows, conflict-free LDSM
#define BLD 136     // B smem row stride: 272B rows, conflict-free LDSM
#define AH_OFF 0
#define AL_OFF (128 * ALD)                       // 5120
#define BH_OFF (2 * 128 * ALD)                   // 10240
#define BL_OFF (2 * 128 * ALD + 32 * BLD)        // 14592
#define STAGE_EL (2 * 128 * ALD + 2 * 32 * BLD)  // 18944 elems / stage
#define WG_SMEM (2 * STAGE_EL * 2)               // 75776 bytes

__global__ __launch_bounds__(256, 2)
void wmma_gemm(const __nv_bfloat16* __restrict__ Ah, const __nv_bfloat16* __restrict__ Al,
               const __nv_bfloat16* __restrict__ Bh, const __nv_bfloat16* __restrict__ Bl,
               float* __restrict__ C, int M, int N, int Kp, int ldc)
{
    extern __shared__ __align__(16) __nv_bfloat16 sm[];

    int tid = threadIdx.x;
    int wid = tid >> 5, lane = tid & 31;
    int wm = wid & 3, wn = wid >> 2;
    int brow = blockIdx.y * 128, bcol = blockIdx.x * 128;
    int ns = Kp >> 5;

    wmma::fragment<wmma::accumulator, 16, 16, 16, float> acc[2][4];
    #pragma unroll
    for (int i = 0; i < 2; i++)
        #pragma unroll
        for (int j = 0; j < 4; j++) wmma::fill_fragment(acc[i][j], 0.f);

    auto load_slab = [&](int k0, int buf) {
        __nv_bfloat16* base = sm + buf * STAGE_EL;
        #pragma unroll
        for (int q = 0; q < 4; q++) {
            int a = tid + (q << 8);                 // 0..1023
            int row = a >> 3, c3 = a & 7, part = c3 >> 2, seg = c3 & 3;
            int gm = brow + row;
            const __nv_bfloat16* srcb = part ? Al : Ah;
            const void* src = (gm < M) ? (const void*)(srcb + (size_t)gm * Kp + k0 + seg * 8)
                                       : (const void*)srcb;
            unsigned int dst = smem_u32(base + (part ? AL_OFF : AH_OFF) + row * ALD + seg * 8);
            cp_async16(dst, src, (gm < M) ? 16 : 0);
        }
        #pragma unroll
        for (int q = 0; q < 4; q++) {
            int b = tid + (q << 8);                 // 0..1023
            int k = b >> 5, c5 = b & 31, part = c5 >> 4, cs = c5 & 15;
            const __nv_bfloat16* srcb = part ? Bl : Bh;
            const void* src = srcb + (size_t)(k0 + k) * NP + bcol + cs * 8;  // NP-padded
            unsigned int dst = smem_u32(base + (part ? BL_OFF : BH_OFF) + k * BLD + cs * 8);
            cp_async16(dst, src, 16);
        }
        asm volatile("cp.async.commit_group;\n");
    };

    load_slab(0, 0);

    for (int it = 0; it < ns; it++) {
        int buf = it & 1;
        if (it + 1 < ns) {
            load_slab((it + 1) << 5, buf ^ 1);
            asm volatile("cp.async.wait_group 1;\n");
        } else {
            asm volatile("cp.async.wait_group 0;\n");
        }
        __syncthreads();

        __nv_bfloat16* base = sm + buf * STAGE_EL;
        #pragma unroll
        for (int ks = 0; ks < 2; ks++) {
            wmma::fragment<wmma::matrix_a, 16, 16, 16, __nv_bfloat16, wmma::row_major> ah[2], al[2];
            #pragma unroll
            for (int i = 0; i < 2; i++) {
                wmma::load_matrix_sync(ah[i], base + AH_OFF + (wm * 32 + i * 16) * ALD + ks * 16, ALD);
                wmma::load_matrix_sync(al[i], base + AL_OFF + (wm * 32 + i * 16) * ALD + ks * 16, ALD);
            }
            #pragma unroll
            for (int j = 0; j < 4; j++) {
                wmma::fragment<wmma::matrix_b, 16, 16, 16, __nv_bfloat16, wmma::row_major> bh, bl;
                wmma::load_matrix_sync(bh, base + BH_OFF + ks * 16 * BLD + wn * 64 + j * 16, BLD);
                wmma::load_matrix_sync(bl, base + BL_OFF + ks * 16 * BLD + wn * 64 + j * 16, BLD);
                #pragma unroll
                for (int i = 0; i < 2; i++) {
                    wmma::mma_sync(acc[i][j], ah[i], bh, acc[i][j]);
                    wmma::mma_sync(acc[i][j], ah[i], bl, acc[i][j]);
                    wmma::mma_sync(acc[i][j], al[i], bh, acc[i][j]);
                }
            }
        }
        __syncthreads();
    }

    // ---- epilogue ----
    if (brow + 128 <= M && bcol + 128 <= N) {
        #pragma unroll
        for (int i = 0; i < 2; i++)
            #pragma unroll
            for (int j = 0; j < 4; j++) {
                int gm0 = brow + wm * 32 + i * 16;
                int gn0 = bcol + wn * 64 + j * 16;
                wmma::store_matrix_sync(&C[(size_t)gm0 * ldc + gn0], acc[i][j], ldc,
                                        wmma::mem_row_major);
            }
    } else {
        float* stagep = (float*)sm + wid * 272;
        __syncthreads();
        #pragma unroll
        for (int i = 0; i < 2; i++)
            #pragma unroll
            for (int j = 0; j < 4; j++) {
                wmma::store_matrix_sync(stagep, acc[i][j], 16, wmma::mem_row_major);
                __syncwarp();
                int gm0 = brow + wm * 32 + i * 16;
                int gn0 = bcol + wn * 64 + j * 16;
                for (int e = lane; e < 256; e += 32) {
                    int r = e >> 4, c = e & 15;
                    int gm = gm0 + r, gn = gn0 + c;
                    if (gm < M && gn < N) C[(size_t)gm * ldc + gn] = stagep[r * 16 + c];
                }
                __syncwarp();
            }
    }
}

// ---------------- fp32 tiled SGEMM for the small FC head ----------------
template<bool RELU_OUT>
__global__ void sgemm_kernel(const float* __restrict__ A, const float* __restrict__ B,
                             const float* __restrict__ bias, float* __restrict__ C,
                             int M, int N, int K, int ldc)
{
    const int BM = 64, BN = 64, BK = 16;
    __shared__ float As[BK][BM + 1];
    __shared__ float Bs[BK][BN + 1];
    int tid = threadIdx.x;
    int tx = tid & 15, ty = tid >> 4;
    int brow = blockIdx.y * BM;
    int bcol = blockIdx.x * BN;

    float acc[4][4];
    #pragma unroll
    for (int i = 0; i < 4; i++)
        #pragma unroll
        for (int j = 0; j < 4; j++) acc[i][j] = 0.f;

    for (int k0 = 0; k0 < K; k0 += BK) {
        #pragma unroll
        for (int i = 0; i < 4; i++) {
            int idx = tid + i * 256;
            int m = idx >> 4, k = idx & 15;
            int gm = brow + m, gk = k0 + k;
            As[k][m] = (gm < M && gk < K) ? A[(size_t)gm * K + gk] : 0.f;
        }
        #pragma unroll
        for (int i = 0; i < 4; i++) {
            int idx = tid + i * 256;
            int k = idx >> 6, n = idx & 63;
            int gk = k0 + k, gn = bcol + n;
            Bs[k][n] = (gk < K && gn < N) ? B[(size_t)gk * N + gn] : 0.f;
        }
        __syncthreads();
        #pragma unroll
        for (int kk = 0; kk < BK; kk++) {
            float a[4], b[4];
            #pragma unroll
            for (int i = 0; i < 4; i++) a[i] = As[kk][ty * 4 + i];
            #pragma unroll
            for (int j = 0; j < 4; j++) b[j] = Bs[kk][tx * 4 + j];
            #pragma unroll
            for (int i = 0; i < 4; i++)
                #pragma unroll
                for (int j = 0; j < 4; j++) acc[i][j] += a[i] * b[j];
        }
        __syncthreads();
    }
    #pragma unroll
    for (int i = 0; i < 4; i++) {
        int gm = brow + ty * 4 + i;
        if (gm >= M) continue;
        #pragma unroll
        for (int j = 0; j < 4; j++) {
            int gn = bcol + tx * 4 + j;
            if (gn >= N) continue;
            float v = acc[i][j] + (bias ? bias[gn] : 0.f);
            if (RELU_OUT) v = fmaxf(v, 0.f);
            C[(size_t)gm * ldc + gn] = v;
        }
    }
}

// ---------------- GAT pass2: weighted accumulation; emits relu'd bf16 hi/lo ----------------
__global__ __launch_bounds__(256)
void k_gat_pass2(const float* __restrict__ bias) {
    int w = (blockIdx.x * blockDim.x + threadIdx.x) >> 5;
    if (w >= NN) return;
    int lane = threadIdx.x & 31;
    int beg = g_off[w], end = g_off[w + 1];

    float ad = 0.f, m = 0.f, inv = 0.f;
    if (lane < NH) {
        ad  = g_asd[w * 20 + 10 + lane];
        m   = g_m[w * NH + lane];
        inv = g_inv[w * NH + lane];
    }

    // precompute per-element head index (loop-invariant)
    int hidx[7][4];
    #pragma unroll
    for (int j = 0; j < 7; j++)
        #pragma unroll
        for (int c = 0; c < 4; c++) {
            int f = 4 * (lane + (j << 5)) + c;
            hidx[j][c] = (f < CC ? f : CC - 1) / FD;
        }

    float4 acc4[7];
    #pragma unroll
    for (int j = 0; j < 7; j++) acc4[j] = make_float4(0.f, 0.f, 0.f, 0.f);

    for (int j = beg; j < end; j++) {
        int s = g_srccsr[j];
        float alpha = 0.f;
        if (lane < NH) {
            float e = g_asd[s * 20 + lane] + ad;
            e = (e > 0.f) ? e : 0.2f * e;
            alpha = expf(e - m) * inv;
        }
        const float4* row4 = (const float4*)(g_bufA + (size_t)s * CC);
        #pragma unroll
        for (int i = 0; i < 7; i++) {
            float a0 = __shfl_sync(0xffffffffu, alpha, hidx[i][0]);
            float a1 = __shfl_sync(0xffffffffu, alpha, hidx[i][1]);
            float a2 = __shfl_sync(0xffffffffu, alpha, hidx[i][2]);
            float a3 = __shfl_sync(0xffffffffu, alpha, hidx[i][3]);
            int q = lane + (i << 5);
            if (q < CC / 4) {
                float4 v = row4[q];
                acc4[i].x += v.x * a0;
                acc4[i].y += v.y * a1;
                acc4[i].z += v.z * a2;
                acc4[i].w += v.w * a3;
            }
        }
    }
    // fused epilogue: relu(gat_out + bias) -> split bf16 hi/lo (row stride KP2)
    #pragma unroll
    for (int i = 0; i < 7; i++) {
        int q = lane + (i << 5);
        if (q < CC / 4) {
            int f0 = q * 4;
            float vv[4] = {acc4[i].x, acc4[i].y, acc4[i].z, acc4[i].w};
            #pragma unroll
            for (int c = 0; c < 4; c++) {
                float v = fmaxf(vv[c] + bias[f0 + c], 0.f);
                __nv_bfloat16 hi = __float2bfloat16(v);
                g_Ah[(size_t)w * KP2 + f0 + c] = hi;
                g_Al[(size_t)w * KP2 + f0 + c] = __float2bfloat16(v - __bfloat162float(hi));
            }
        }
    }
    // zero-fill K padding [780, 800)
    if (lane < KP2 - CC) {
        int f = CC + lane;
        g_Ah[(size_t)w * KP2 + f] = __float2bfloat16(0.f);
        g_Al[(size_t)w * KP2 + f] = __float2bfloat16(0.f);
    }
}

// ---------------- fused GCN gather: one warp per dst node, float4, relu'd output ----------------
__global__ __launch_bounds__(256)
void k_gcn_gather(const float* __restrict__ bias) {
    int w = (blockIdx.x * blockDim.x + threadIdx.x) >> 5;
    if (w >= NN) return;
    int lane = threadIdx.x & 31;
    int beg = g_off[w], end = g_off[w + 1];
    float dv = g_dinv[w];

    float4 acc4[7];
    #pragma unroll
    for (int i = 0; i < 7; i++) acc4[i] = make_float4(0.f, 0.f, 0.f, 0.f);

    for (int j = beg; j < end; j++) {
        int s = g_srccsr[j];
        float nr = g_dinv[s] * dv;
        const float4* row4 = (const float4*)(g_bufA + (size_t)s * CC);
        #pragma unroll
        for (int i = 0; i < 7; i++) {
            int q = lane + (i << 5);
            if (q < CC / 4) {
                float4 v = row4[q];
                acc4[i].x += v.x * nr;
                acc4[i].y += v.y * nr;
                acc4[i].z += v.z * nr;
                acc4[i].w += v.w * nr;
            }
        }
    }
    const float4* bias4 = (const float4*)bias;
    float4* out4 = (float4*)(g_bufB + (size_t)w * CC);
    #pragma unroll
    for (int i = 0; i < 7; i++) {
        int q = lane + (i << 5);
        if (q < CC / 4) {
            float4 b = bias4[q];
            float4 o;
            o.x = fmaxf(acc4[i].x + b.x, 0.f);
            o.y = fmaxf(acc4[i].y + b.y, 0.f);
            o.z = fmaxf(acc4[i].z + b.z, 0.f);
            o.w = fmaxf(acc4[i].w + b.w, 0.f);
            out4[q] = o;
        }
    }
}

// ---------------- pooling (batch sorted -> contiguous ranges; input pre-relu'd) ----------------
__global__ void k_pool2() {
    int b = blockIdx.y;
    int f = blockIdx.x * 256 + threadIdx.x;
    if (f >= CC) return;
    int s = g_bstart[b], e = g_bstart[b + 1];
    float mx = 0.f, sm = 0.f;
    int n = s;
    // 4-way unrolled scan for MLP
    for (; n + 3 < e; n += 4) {
        float v0 = g_bufB[(size_t)(n + 0) * CC + f];
        float v1 = g_bufB[(size_t)(n + 1) * CC + f];
        float v2 = g_bufB[(size_t)(n + 2) * CC + f];
        float v3 = g_bufB[(size_t)(n + 3) * CC + f];
        mx = fmaxf(mx, fmaxf(fmaxf(v0, v1), fmaxf(v2, v3)));
        sm += (v0 + v1) + (v2 + v3);
    }
    for (; n < e; n++) {
        float v = g_bufB[(size_t)n * CC + f];
        mx = fmaxf(mx, v);
        sm += v;
    }
    g_g[b * 1560 + f] = mx;
    g_g[b * 1560 + 780 + f] = sm / fmaxf((float)(e - s), 1.f);
}

// ---------------- protein branches ----------------
__global__ void k_conv2(const int* __restrict__ t2, const float* __restrict__ emb,
                        const float* __restrict__ Wc2, const float* __restrict__ bc2)
{
    __shared__ float wag[26 * 256];
    int b = blockIdx.x;
    int tid = threadIdx.x;
    for (int v = 0; v < 26; v++) wag[v * 256 + tid] = 0.f;
    __syncthreads();
    int o = tid >> 3, k = tid & 7;
    const float* wcol = &Wc2[o * 8000 + k];
    const int* t2b = &t2[b * 1000];
    for (int i = 0; i < 1000; i++) {
        int v = t2b[i];
        wag[v * 256 + tid] += wcol[i * 8];
    }
    __syncthreads();
    for (int j = tid; j < 32 * 121; j += 256) {
        int oo = j / 121, l = j % 121;
        float acc = bc2[oo];
        for (int v = 0; v < 26; v++) {
            const float* wa = &wag[v * 256 + oo * 8];
            const float* er = &emb[v * 128 + l];
            #pragma unroll
            for (int kk = 0; kk < 8; kk++) acc += wa[kk] * er[kk];
        }
        g_xt2c[b * 3872 + j] = acc;
    }
}

__global__ void k_conv1(const float* __restrict__ t1, const float* __restrict__ Wc1,
                        const float* __restrict__ bc1)
{
    int b = blockIdx.x;
    int tid = threadIdx.x;
    int o = tid / 17, l = tid % 17;
    float acc = bc1[o];
    for (int i = 0; i < 20; i++) {
        const float* xr = &t1[b * 480 + i * 24 + l];
        const float* wr = &Wc1[o * 160 + i * 8];
        #pragma unroll
        for (int k = 0; k < 8; k++) acc += xr[k] * wr[k];
    }
    g_xt1c[b * 544 + tid] = acc;
}

// ---------------- launch ----------------
static inline dim3 gemm_grid(int M, int N) {
    return dim3((N + 63) / 64, (M + 63) / 64);
}

extern "C" void kernel_launch(void* const* d_in, const int* in_sizes, int n_in,
                              void* d_out, int out_size)
{
    const float* x       = (const float*)d_in[0];
    const int*   ei      = (const int*)  d_in[1];
    const int*   batch   = (const int*)  d_in[2];
    const float* target1 = (const float*)d_in[3];
    const int*   target2 = (const int*)  d_in[4];
    const float* W_gat   = (const float*)d_in[5];
    const float* att_src = (const float*)d_in[6];
    const float* att_dst = (const float*)d_in[7];
    const float* b_gat   = (const float*)d_in[8];
    const float* W_gcn   = (const float*)d_in[9];
    const float* b_gcn   = (const float*)d_in[10];
    const float* W_fcg1  = (const float*)d_in[11];
    const float* b_fcg1  = (const float*)d_in[12];
    const float* W_fcg2  = (const float*)d_in[13];
    const float* b_fcg2  = (const float*)d_in[14];
    const float* emb     = (const float*)d_in[15];
    const float* Wc2     = (const float*)d_in[16];
    const float* bc2     = (const float*)d_in[17];
    const float* W_fc2xt = (const float*)d_in[18];
    const float* b_fc2xt = (const float*)d_in[19];
    const float* Wc1     = (const float*)d_in[20];
    const float* bc1     = (const float*)d_in[21];
    const float* W_fc1xt = (const float*)d_in[22];
    const float* b_fc1xt = (const float*)d_in[23];
    const float* W_fc1   = (const float*)d_in[24];
    const float* b_fc1   = (const float*)d_in[25];
    const float* W_fc2   = (const float*)d_in[26];
    const float* b_fc2   = (const float*)d_in[27];
    const float* W_out   = (const float*)d_in[28];
    const float* b_out   = (const float*)d_in[29];
    float* out = (float*)d_out;

    int E0 = in_sizes[1] / 2;           // 150000
    int E  = E0 + NN;                   // + self loops

    // one-time host-side setup (no device allocations)
    static cudaStream_t s2 = nullptr, s3 = nullptr;
    static cudaEvent_t evFork = nullptr, evP1 = nullptr, evB2 = nullptr, evXt = nullptr, evAsd = nullptr;
    if (!s2) {
        cudaStreamCreateWithFlags(&s2, cudaStreamNonBlocking);
        cudaStreamCreateWithFlags(&s3, cudaStreamNonBlocking);
        cudaEventCreateWithFlags(&evFork, cudaEventDisableTiming);
        cudaEventCreateWithFlags(&evP1,   cudaEventDisableTiming);
        cudaEventCreateWithFlags(&evB2,   cudaEventDisableTiming);
        cudaEventCreateWithFlags(&evXt,   cudaEventDisableTiming);
        cudaEventCreateWithFlags(&evAsd,  cudaEventDisableTiming);
        cudaFuncSetAttribute(wmma_gemm, cudaFuncAttributeMaxDynamicSharedMemorySize, WG_SMEM);
    }

    float *bufA, *pg, *pt1, *pxc, *pxt2c, *pxt1c, *pf1, *pf2, *pwproj, *pasd;
    __nv_bfloat16 *pAh, *pAl, *pBh1, *pBl1, *pBh2, *pBl2;
    cudaGetSymbolAddress((void**)&bufA,  g_bufA);
    cudaGetSymbolAddress((void**)&pAh,   g_Ah);
    cudaGetSymbolAddress((void**)&pAl,   g_Al);
    cudaGetSymbolAddress((void**)&pBh1,  g_Bh1);
    cudaGetSymbolAddress((void**)&pBl1,  g_Bl1);
    cudaGetSymbolAddress((void**)&pBh2,  g_Bh2);
    cudaGetSymbolAddress((void**)&pBl2,  g_Bl2);
    cudaGetSymbolAddress((void**)&pwproj, g_wproj);
    cudaGetSymbolAddress((void**)&pasd,  g_asd);
    cudaGetSymbolAddress((void**)&pg,    g_g);
    cudaGetSymbolAddress((void**)&pt1,   g_t1);
    cudaGetSymbolAddress((void**)&pxc,   g_xc);
    cudaGetSymbolAddress((void**)&pxt2c, g_xt2c);
    cudaGetSymbolAddress((void**)&pxt1c, g_xt1c);
    cudaGetSymbolAddress((void**)&pf1,   g_f1);
    cudaGetSymbolAddress((void**)&pf2,   g_f2);

    dim3 wg_grid(7, (NN + 127) / 128);   // N tiles x M tiles

    // ---- fork ----
    cudaEventRecord(evFork, 0);
    cudaStreamWaitEvent(s2, evFork, 0);
    cudaStreamWaitEvent(s3, evFork, 0);

    // ---- stream s3: attention stats + GEMM2 B-conversion + protein branch ----
    {
        k_wproj<<<(FD * 20 + 255) / 256, 256, 0, s3>>>(W_gat, att_src, att_dst);
        sgemm_kernel<false><<<gemm_grid(NN, 20), 256, 0, s3>>>(x, pwproj, nullptr, pasd, NN, 20, FD, 20);
        cudaEventRecord(evAsd, s3);
        size_t nb2 = (size_t)KP2 * NP;
        k_convB<<<(int)((nb2 + 255) / 256), 256, 0, s3>>>(W_gcn, CC, CC, KP2, pBh2, pBl2);
        cudaEventRecord(evB2, s3);
        k_conv2<<<NB, 256, 0, s3>>>(target2, emb, Wc2, bc2);
        sgemm_kernel<false><<<gemm_grid(NB, 128), 256, 0, s3>>>(pxt2c, W_fc2xt, b_fc2xt, pxc + 256, NB, 128, 3872, 384);
        k_conv1<<<NB, 544, 0, s3>>>(target1, Wc1, bc1);
        sgemm_kernel<false><<<gemm_grid(NB, 128), 256, 0, s3>>>(pxt1c, W_fc1xt, b_fc1xt, pxc + 128, NB, 128, 544, 384);
        cudaEventRecord(evXt, s3);
    }

    // ---- stream s2: CSR chain + batch boundaries, then softmax pass1 (needs asd) ----
    k_zero_deg<<<(NN + 255) / 256, 256, 0, s2>>>();
    k_count<<<(E + 255) / 256, 256, 0, s2>>>(ei, E0, E);
    k_scan1<<<NBLK, 1024, 0, s2>>>();
    k_scan2<<<1, 64, 0, s2>>>();
    k_scan3<<<(NN + 255) / 256, 256, 0, s2>>>();
    k_fillcsr<<<(E + 255) / 256, 256, 0, s2>>>(ei, E0, E);
    k_bstart<<<(NN + 255) / 256, 256, 0, s2>>>(batch);
    cudaStreamWaitEvent(s2, evAsd, 0);
    k_gat_pass1<<<(NN * 32 + 255) / 256, 256, 0, s2>>>();
    cudaEventRecord(evP1, s2);

    // ---- default stream: GNN critical path ----
    // h = x @ W_gat (split-bf16 wmma)
    {
        size_t na = (size_t)NN * KP1;
        k_convA<false><<<(int)((na + 255) / 256), 256>>>(x, NN, FD, KP1, pAh, pAl);
        size_t nb = (size_t)KP1 * NP;
        k_convB<<<(int)((nb + 255) / 256), 256>>>(W_gat, FD, CC, KP1, pBh1, pBl1);
        wmma_gemm<<<wg_grid, 256, WG_SMEM>>>(pAh, pAl, pBh1, pBl1, bufA, NN, CC, KP1, CC);
    }

    // GAT pass2 (needs h + CSR + softmax stats -> join s2)
    cudaStreamWaitEvent(0, evP1, 0);
    k_gat_pass2<<<(NN * 32 + 255) / 256, 256>>>(b_gat);

    // hg = relu(gat_out) @ W_gcn (needs convB2 -> join s3's evB2)
    cudaStreamWaitEvent(0, evB2, 0);
    wmma_gemm<<<wg_grid, 256, WG_SMEM>>>(pAh, pAl, pBh2, pBl2, bufA, NN, CC, KP2, CC);

    // GCN gather + pooling
    k_gcn_gather<<<(NN * 32 + 255) / 256, 256>>>(b_gcn);
    k_pool2<<<dim3(4, NB), 256>>>();

    // graph MLP head
    sgemm_kernel<true ><<<gemm_grid(NB, 1500), 256>>>(pg,  W_fcg1, b_fcg1, pt1, NB, 1500, 1560, 1500);
    sgemm_kernel<false><<<gemm_grid(NB, 128),  256>>>(pt1, W_fcg2, b_fcg2, pxc + 0, NB, 128, 1500, 384);

    // final MLP (needs xt branches -> join s3)
    cudaStreamWaitEvent(0, evXt, 0);
    sgemm_kernel<true ><<<gemm_grid(NB, 1024), 256>>>(pxc, W_fc1, b_fc1, pf1, NB, 1024, 384, 1024);
    sgemm_kernel<true ><<<gemm_grid(NB, 512),  256>>>(pf1, W_fc2, b_fc2, pf2, NB, 512, 1024, 512);
    sgemm_kernel<false><<<gemm_grid(NB, 1),    256>>>(pf2, W_out, b_out, out, NB, 1, 512, 1);
}

// round 17
// speedup vs baseline: 1.0153x; 1.0153x over previous
#include <cuda_runtime.h>
#include <cuda_bf16.h>
#include <mma.h>
#include <math.h>
#include <cstdint>

using namespace nvcuda;

// ---------------- problem constants ----------------
#define NN 50000      // nodes
#define NB 128        // graphs / batch
#define NH 10         // heads
#define FD 78         // per-head feature
#define CC 780        // NH*FD
#define E0MAX 150000
#define EMAX  (E0MAX + NN)   // edges incl self loops
#define KP1 96               // GEMM1 K (78) padded to mult of 32
#define KP2 800              // GEMM2 K (780) padded to mult of 32
#define NP  896              // N padded (7*128) for B tiles
#define NBLK 49              // ceil(NN/1024)

// ---------------- scratch (device globals; no allocs) ----------------
__device__ float g_bufA[NN * CC];   // h = x@W_gat, later hg = relu(gat)@W_gcn
__device__ float g_bufB[NN * CC];   // relu(gcn_out)
__device__ __nv_bfloat16 g_Ah[NN * KP2];
__device__ __nv_bfloat16 g_Al[NN * KP2];
__device__ __nv_bfloat16 g_Bh1[KP1 * NP];   // GEMM1 B
__device__ __nv_bfloat16 g_Bl1[KP1 * NP];
__device__ __nv_bfloat16 g_Bh2[KP2 * NP];   // GEMM2 B
__device__ __nv_bfloat16 g_Bl2[KP2 * NP];
__device__ float g_wproj[FD * 20];  // [78][20]: cols 0..9 = W@att_src per head, 10..19 = W@att_dst
__device__ float g_asd[NN * 20];    // [n][20]: as (0..9), ad (10..19)
__device__ float g_m[NN * NH];
__device__ float g_inv[NN * NH];
__device__ int   g_degi[NN];
__device__ int   g_off[NN + 1];
__device__ int   g_cur[NN];
__device__ int   g_srccsr[EMAX];
__device__ float g_dinv[NN];
__device__ int   g_bstart[NB + 1];
__device__ int   g_bsum[64];
__device__ int   g_bsum2[64];
__device__ float g_g[NB * 1560];
__device__ float g_t1[NB * 1500];
__device__ float g_xc[NB * 384];
__device__ float g_xt2c[NB * 3872];
__device__ float g_xt1c[NB * 544];
__device__ float g_f1[NB * 1024];
__device__ float g_f2[NB * 512];

// ---------------- helpers ----------------
__device__ __forceinline__ void edge_sd(const int* ei, int E0, int e, int& s, int& d) {
    if (e < E0) { s = ei[e]; d = ei[E0 + e]; }
    else        { s = e - E0; d = e - E0; }
}

__device__ __forceinline__ void cp_async16(unsigned int smem, const void* gmem, int srcbytes) {
    asm volatile("cp.async.cg.shared.global [%0], [%1], 16, %2;\n"
                 :: "r"(smem), "l"(gmem), "r"(srcbytes));
}
__device__ __forceinline__ unsigned int smem_u32(const void* p) {
    return (unsigned int)__cvta_generic_to_shared(p);
}

// ---------------- CSR build ----------------
__global__ void k_zero_deg() {
    int i = blockIdx.x * blockDim.x + threadIdx.x;
    if (i < NN) g_degi[i] = 0;
}

__global__ void k_count(const int* __restrict__ ei, int E0, int E) {
    int e = blockIdx.x * blockDim.x + threadIdx.x;
    if (e >= E) return;
    int s, d; edge_sd(ei, E0, e, s, d);
    (void)s;
    atomicAdd(&g_degi[d], 1);
}

__global__ void k_scan1() {
    __shared__ int sh[1024];
    int tid = threadIdx.x;
    int i = blockIdx.x * 1024 + tid;
    int v = (i < NN) ? g_degi[i] : 0;
    sh[tid] = v;
    __syncthreads();
    #pragma unroll
    for (int o = 1; o < 1024; o <<= 1) {
        int t = (tid >= o) ? sh[tid - o] : 0;
        __syncthreads();
        sh[tid] += t;
        __syncthreads();
    }
    if (i < NN) g_off[i] = sh[tid] - v;      // block-local exclusive
    if (tid == 1023) g_bsum[blockIdx.x] = sh[1023];
}

__global__ void k_scan2() {
    __shared__ int sh[64];
    int t = threadIdx.x;
    int v = (t < NBLK) ? g_bsum[t] : 0;
    sh[t] = v;
    __syncthreads();
    #pragma unroll
    for (int o = 1; o < 64; o <<= 1) {
        int x = (t >= o) ? sh[t - o] : 0;
        __syncthreads();
        sh[t] += x;
        __syncthreads();
    }
    if (t < NBLK) g_bsum2[t] = sh[t] - v;    // exclusive
    if (t == 63) g_off[NN] = sh[63];         // total
}

// fused: finalize offsets + init cursors + dinv
__global__ void k_scan3() {
    int i = blockIdx.x * blockDim.x + threadIdx.x;
    if (i >= NN) return;
    int off = g_off[i] + g_bsum2[i >> 10];
    g_off[i] = off;
    g_cur[i] = off;
    float dg = (float)g_degi[i];
    g_dinv[i] = (dg > 0.f) ? rsqrtf(dg) : 0.f;
}

__global__ void k_fillcsr(const int* __restrict__ ei, int E0, int E) {
    int e = blockIdx.x * blockDim.x + threadIdx.x;
    if (e >= E) return;
    int s, d; edge_sd(ei, E0, e, s, d);
    int pos = atomicAdd(&g_cur[d], 1);
    g_srccsr[pos] = s;
}

__global__ void k_bstart(const int* __restrict__ batch) {
    int n = blockIdx.x * blockDim.x + threadIdx.x;
    if (n >= NN) return;
    int bn = batch[n];
    int bp = (n == 0) ? -1 : batch[n - 1];
    for (int g = bp + 1; g <= bn; g++) g_bstart[g] = n;
    if (n == NN - 1)
        for (int g = bn + 1; g <= NB; g++) g_bstart[g] = NN;
}

// ---------------- projected attention weights: wproj = W_gat (per-head) @ att ----------------
__global__ void k_wproj(const float* __restrict__ W, const float* __restrict__ att_src,
                        const float* __restrict__ att_dst) {
    int t = blockIdx.x * blockDim.x + threadIdx.x;
    if (t >= FD * 20) return;
    int i = t / 20, j = t % 20;
    int h = j % NH;
    const float* att = (j >= NH) ? att_dst : att_src;
    float s = 0.f;
    #pragma unroll 6
    for (int f = 0; f < FD; f++) s += W[(size_t)i * CC + h * FD + f] * att[h * FD + f];
    g_wproj[i * 20 + j] = s;
}

// ---------------- GAT softmax pass1: per-node online softmax over incident edges ----------------
__global__ __launch_bounds__(256)
void k_gat_pass1() {
    int w = (blockIdx.x * blockDim.x + threadIdx.x) >> 5;
    if (w >= NN) return;
    int lane = threadIdx.x & 31;
    int beg = g_off[w], end = g_off[w + 1];
    float ad = (lane < NH) ? g_asd[w * 20 + 10 + lane] : 0.f;
    float m = -1e30f, ssum = 0.f;
    for (int j = beg; j < end; j++) {
        int s = g_srccsr[j];
        if (lane < NH) {
            float e = g_asd[s * 20 + lane] + ad;
            e = (e > 0.f) ? e : 0.2f * e;
            float mn = fmaxf(m, e);
            ssum = ssum * expf(m - mn) + expf(e - mn);
            m = mn;
        }
    }
    if (lane < NH) {
        g_m[w * NH + lane] = m;
        g_inv[w * NH + lane] = 1.f / (ssum + 1e-16f);
    }
}

// ---------------- split-bf16 conversion ----------------
template<bool RELU>
__global__ void k_convA(const float* __restrict__ src, int M, int K, int Kp,
                        __nv_bfloat16* __restrict__ Ah, __nv_bfloat16* __restrict__ Al)
{
    size_t idx = (size_t)blockIdx.x * blockDim.x + threadIdx.x;
    if (idx >= (size_t)M * Kp) return;
    int c = (int)(idx % Kp);
    int r = (int)(idx / Kp);
    float v = 0.f;
    if (c < K) {
        v = src[(size_t)r * K + c];
        if (RELU) v = fmaxf(v, 0.f);
    }
    __nv_bfloat16 h = __float2bfloat16(v);
    Ah[idx] = h;
    Al[idx] = __float2bfloat16(v - __bfloat162float(h));
}

// B stored [k][NP] row-major, zero-padded columns/rows
__global__ void k_convB(const float* __restrict__ W, int K, int N, int Kp,
                        __nv_bfloat16* __restrict__ Bh, __nv_bfloat16* __restrict__ Bl)
{
    size_t idx = (size_t)blockIdx.x * blockDim.x + threadIdx.x;
    if (idx >= (size_t)Kp * NP) return;
    int n = (int)(idx % NP);
    int k = (int)(idx / NP);
    float v = (k < K && n < N) ? W[(size_t)k * N + n] : 0.f;
    __nv_bfloat16 h = __float2bfloat16(v);
    Bh[idx] = h;
    Bl[idx] = __float2bfloat16(v - __bfloat162float(h));
}

// ---------------- split-bf16 wmma GEMM v3 (BK=32, 2-stage, dynamic smem) ----------------
#define ALD 40      // A smem row stride (elems): 80B rows, conflict-free LDSM
#define BLD 136     // B smem row stride: 272B rows, conflict-free LDSM
#define AH_OFF 0
#define AL_OFF (128 * ALD)                       // 5120
#define BH_OFF (2 * 128 * ALD)                   // 10240
#define BL_OFF (2 * 128 * ALD + 32 * BLD)        // 14592
#define STAGE_EL (2 * 128 * ALD + 2 * 32 * BLD)  // 18944 elems / stage
#define WG_SMEM (2 * STAGE_EL * 2)               // 75776 bytes

__global__ __launch_bounds__(256, 2)
void wmma_gemm(const __nv_bfloat16* __restrict__ Ah, const __nv_bfloat16* __restrict__ Al,
               const __nv_bfloat16* __restrict__ Bh, const __nv_bfloat16* __restrict__ Bl,
               float* __restrict__ C, int M, int N, int Kp, int ldc)
{
    extern __shared__ __align__(16) __nv_bfloat16 sm[];

    int tid = threadIdx.x;
    int wid = tid >> 5, lane = tid & 31;
    int wm = wid & 3, wn = wid >> 2;
    int brow = blockIdx.y * 128, bcol = blockIdx.x * 128;
    int ns = Kp >> 5;

    wmma::fragment<wmma::accumulator, 16, 16, 16, float> acc[2][4];
    #pragma unroll
    for (int i = 0; i < 2; i++)
        #pragma unroll
        for (int j = 0; j < 4; j++) wmma::fill_fragment(acc[i][j], 0.f);

    auto load_slab = [&](int k0, int buf) {
        __nv_bfloat16* base = sm + buf * STAGE_EL;
        #pragma unroll
        for (int q = 0; q < 4; q++) {
            int a = tid + (q << 8);                 // 0..1023
            int row = a >> 3, c3 = a & 7, part = c3 >> 2, seg = c3 & 3;
            int gm = brow + row;
            const __nv_bfloat16* srcb = part ? Al : Ah;
            const void* src = (gm < M) ? (const void*)(srcb + (size_t)gm * Kp + k0 + seg * 8)
                                       : (const void*)srcb;
            unsigned int dst = smem_u32(base + (part ? AL_OFF : AH_OFF) + row * ALD + seg * 8);
            cp_async16(dst, src, (gm < M) ? 16 : 0);
        }
        #pragma unroll
        for (int q = 0; q < 4; q++) {
            int b = tid + (q << 8);                 // 0..1023
            int k = b >> 5, c5 = b & 31, part = c5 >> 4, cs = c5 & 15;
            const __nv_bfloat16* srcb = part ? Bl : Bh;
            const void* src = srcb + (size_t)(k0 + k) * NP + bcol + cs * 8;  // NP-padded
            unsigned int dst = smem_u32(base + (part ? BL_OFF : BH_OFF) + k * BLD + cs * 8);
            cp_async16(dst, src, 16);
        }
        asm volatile("cp.async.commit_group;\n");
    };

    load_slab(0, 0);

    for (int it = 0; it < ns; it++) {
        int buf = it & 1;
        if (it + 1 < ns) {
            load_slab((it + 1) << 5, buf ^ 1);
            asm volatile("cp.async.wait_group 1;\n");
        } else {
            asm volatile("cp.async.wait_group 0;\n");
        }
        __syncthreads();

        __nv_bfloat16* base = sm + buf * STAGE_EL;
        #pragma unroll
        for (int ks = 0; ks < 2; ks++) {
            wmma::fragment<wmma::matrix_a, 16, 16, 16, __nv_bfloat16, wmma::row_major> ah[2], al[2];
            #pragma unroll
            for (int i = 0; i < 2; i++) {
                wmma::load_matrix_sync(ah[i], base + AH_OFF + (wm * 32 + i * 16) * ALD + ks * 16, ALD);
                wmma::load_matrix_sync(al[i], base + AL_OFF + (wm * 32 + i * 16) * ALD + ks * 16, ALD);
            }
            #pragma unroll
            for (int j = 0; j < 4; j++) {
                wmma::fragment<wmma::matrix_b, 16, 16, 16, __nv_bfloat16, wmma::row_major> bh, bl;
                wmma::load_matrix_sync(bh, base + BH_OFF + ks * 16 * BLD + wn * 64 + j * 16, BLD);
                wmma::load_matrix_sync(bl, base + BL_OFF + ks * 16 * BLD + wn * 64 + j * 16, BLD);
                #pragma unroll
                for (int i = 0; i < 2; i++) {
                    wmma::mma_sync(acc[i][j], ah[i], bh, acc[i][j]);
                    wmma::mma_sync(acc[i][j], ah[i], bl, acc[i][j]);
                    wmma::mma_sync(acc[i][j], al[i], bh, acc[i][j]);
                }
            }
        }
        __syncthreads();
    }

    // ---- epilogue ----
    if (brow + 128 <= M && bcol + 128 <= N) {
        #pragma unroll
        for (int i = 0; i < 2; i++)
            #pragma unroll
            for (int j = 0; j < 4; j++) {
                int gm0 = brow + wm * 32 + i * 16;
                int gn0 = bcol + wn * 64 + j * 16;
                wmma::store_matrix_sync(&C[(size_t)gm0 * ldc + gn0], acc[i][j], ldc,
                                        wmma::mem_row_major);
            }
    } else {
        float* stagep = (float*)sm + wid * 272;
        __syncthreads();
        #pragma unroll
        for (int i = 0; i < 2; i++)
            #pragma unroll
            for (int j = 0; j < 4; j++) {
                wmma::store_matrix_sync(stagep, acc[i][j], 16, wmma::mem_row_major);
                __syncwarp();
                int gm0 = brow + wm * 32 + i * 16;
                int gn0 = bcol + wn * 64 + j * 16;
                for (int e = lane; e < 256; e += 32) {
                    int r = e >> 4, c = e & 15;
                    int gm = gm0 + r, gn = gn0 + c;
                    if (gm < M && gn < N) C[(size_t)gm * ldc + gn] = stagep[r * 16 + c];
                }
                __syncwarp();
            }
    }
}

// ---------------- fp32 tiled SGEMM for the small FC head ----------------
template<bool RELU_OUT>
__global__ void sgemm_kernel(const float* __restrict__ A, const float* __restrict__ B,
                             const float* __restrict__ bias, float* __restrict__ C,
                             int M, int N, int K, int ldc)
{
    const int BM = 64, BN = 64, BK = 16;
    __shared__ float As[BK][BM + 1];
    __shared__ float Bs[BK][BN + 1];
    int tid = threadIdx.x;
    int tx = tid & 15, ty = tid >> 4;
    int brow = blockIdx.y * BM;
    int bcol = blockIdx.x * BN;

    float acc[4][4];
    #pragma unroll
    for (int i = 0; i < 4; i++)
        #pragma unroll
        for (int j = 0; j < 4; j++) acc[i][j] = 0.f;

    for (int k0 = 0; k0 < K; k0 += BK) {
        #pragma unroll
        for (int i = 0; i < 4; i++) {
            int idx = tid + i * 256;
            int m = idx >> 4, k = idx & 15;
            int gm = brow + m, gk = k0 + k;
            As[k][m] = (gm < M && gk < K) ? A[(size_t)gm * K + gk] : 0.f;
        }
        #pragma unroll
        for (int i = 0; i < 4; i++) {
            int idx = tid + i * 256;
            int k = idx >> 6, n = idx & 63;
            int gk = k0 + k, gn = bcol + n;
            Bs[k][n] = (gk < K && gn < N) ? B[(size_t)gk * N + gn] : 0.f;
        }
        __syncthreads();
        #pragma unroll
        for (int kk = 0; kk < BK; kk++) {
            float a[4], b[4];
            #pragma unroll
            for (int i = 0; i < 4; i++) a[i] = As[kk][ty * 4 + i];
            #pragma unroll
            for (int j = 0; j < 4; j++) b[j] = Bs[kk][tx * 4 + j];
            #pragma unroll
            for (int i = 0; i < 4; i++)
                #pragma unroll
                for (int j = 0; j < 4; j++) acc[i][j] += a[i] * b[j];
        }
        __syncthreads();
    }
    #pragma unroll
    for (int i = 0; i < 4; i++) {
        int gm = brow + ty * 4 + i;
        if (gm >= M) continue;
        #pragma unroll
        for (int j = 0; j < 4; j++) {
            int gn = bcol + tx * 4 + j;
            if (gn >= N) continue;
            float v = acc[i][j] + (bias ? bias[gn] : 0.f);
            if (RELU_OUT) v = fmaxf(v, 0.f);
            C[(size_t)gm * ldc + gn] = v;
        }
    }
}

// ---------------- GAT pass2: weighted accumulation; emits relu'd bf16 hi/lo ----------------
__global__ __launch_bounds__(256)
void k_gat_pass2(const float* __restrict__ bias) {
    int w = (blockIdx.x * blockDim.x + threadIdx.x) >> 5;
    if (w >= NN) return;
    int lane = threadIdx.x & 31;
    int beg = g_off[w], end = g_off[w + 1];
    if (beg >= end) return;   // self-loops guarantee >=1, but keep safe

    float ad = 0.f, m = 0.f, inv = 0.f;
    if (lane < NH) {
        ad  = g_asd[w * 20 + 10 + lane];
        m   = g_m[w * NH + lane];
        inv = g_inv[w * NH + lane];
    }

    // precompute per-element head index (loop-invariant)
    int hidx[7][4];
    #pragma unroll
    for (int j = 0; j < 7; j++)
        #pragma unroll
        for (int c = 0; c < 4; c++) {
            int f = 4 * (lane + (j << 5)) + c;
            hidx[j][c] = (f < CC ? f : CC - 1) / FD;
        }

    float4 acc4[7];
    #pragma unroll
    for (int j = 0; j < 7; j++) acc4[j] = make_float4(0.f, 0.f, 0.f, 0.f);

    int s = g_srccsr[beg];
    for (int j = beg; j < end; j++) {
        int s_next = (j + 1 < end) ? g_srccsr[j + 1] : s;   // prefetch next index
        float alpha = 0.f;
        if (lane < NH) {
            float e = g_asd[s * 20 + lane] + ad;
            e = (e > 0.f) ? e : 0.2f * e;
            alpha = expf(e - m) * inv;
        }
        const float4* row4 = (const float4*)(g_bufA + (size_t)s * CC);
        #pragma unroll
        for (int i = 0; i < 7; i++) {
            float a0 = __shfl_sync(0xffffffffu, alpha, hidx[i][0]);
            float a1 = __shfl_sync(0xffffffffu, alpha, hidx[i][1]);
            float a2 = __shfl_sync(0xffffffffu, alpha, hidx[i][2]);
            float a3 = __shfl_sync(0xffffffffu, alpha, hidx[i][3]);
            int q = lane + (i << 5);
            if (q < CC / 4) {
                float4 v = row4[q];
                acc4[i].x += v.x * a0;
                acc4[i].y += v.y * a1;
                acc4[i].z += v.z * a2;
                acc4[i].w += v.w * a3;
            }
        }
        s = s_next;
    }
    // fused epilogue: relu(gat_out + bias) -> split bf16 hi/lo (row stride KP2)
    #pragma unroll
    for (int i = 0; i < 7; i++) {
        int q = lane + (i << 5);
        if (q < CC / 4) {
            int f0 = q * 4;
            float vv[4] = {acc4[i].x, acc4[i].y, acc4[i].z, acc4[i].w};
            #pragma unroll
            for (int c = 0; c < 4; c++) {
                float v = fmaxf(vv[c] + bias[f0 + c], 0.f);
                __nv_bfloat16 hi = __float2bfloat16(v);
                g_Ah[(size_t)w * KP2 + f0 + c] = hi;
                g_Al[(size_t)w * KP2 + f0 + c] = __float2bfloat16(v - __bfloat162float(hi));
            }
        }
    }
    // zero-fill K padding [780, 800)
    if (lane < KP2 - CC) {
        int f = CC + lane;
        g_Ah[(size_t)w * KP2 + f] = __float2bfloat16(0.f);
        g_Al[(size_t)w * KP2 + f] = __float2bfloat16(0.f);
    }
}

// ---------------- fused GCN gather: one warp per dst node, float4, relu'd output ----------------
__global__ __launch_bounds__(256)
void k_gcn_gather(const float* __restrict__ bias) {
    int w = (blockIdx.x * blockDim.x + threadIdx.x) >> 5;
    if (w >= NN) return;
    int lane = threadIdx.x & 31;
    int beg = g_off[w], end = g_off[w + 1];
    float dv = g_dinv[w];

    float4 acc4[7];
    #pragma unroll
    for (int i = 0; i < 7; i++) acc4[i] = make_float4(0.f, 0.f, 0.f, 0.f);

    if (beg < end) {
        int s = g_srccsr[beg];
        for (int j = beg; j < end; j++) {
            int s_next = (j + 1 < end) ? g_srccsr[j + 1] : s;   // prefetch next index
            float nr = g_dinv[s] * dv;
            const float4* row4 = (const float4*)(g_bufA + (size_t)s * CC);
            #pragma unroll
            for (int i = 0; i < 7; i++) {
                int q = lane + (i << 5);
                if (q < CC / 4) {
                    float4 v = row4[q];
                    acc4[i].x += v.x * nr;
                    acc4[i].y += v.y * nr;
                    acc4[i].z += v.z * nr;
                    acc4[i].w += v.w * nr;
                }
            }
            s = s_next;
        }
    }
    const float4* bias4 = (const float4*)bias;
    float4* out4 = (float4*)(g_bufB + (size_t)w * CC);
    #pragma unroll
    for (int i = 0; i < 7; i++) {
        int q = lane + (i << 5);
        if (q < CC / 4) {
            float4 b = bias4[q];
            float4 o;
            o.x = fmaxf(acc4[i].x + b.x, 0.f);
            o.y = fmaxf(acc4[i].y + b.y, 0.f);
            o.z = fmaxf(acc4[i].z + b.z, 0.f);
            o.w = fmaxf(acc4[i].w + b.w, 0.f);
            out4[q] = o;
        }
    }
}

// ---------------- pooling (batch sorted -> contiguous ranges; input pre-relu'd) ----------------
__global__ void k_pool2() {
    int b = blockIdx.y;
    int f = blockIdx.x * 256 + threadIdx.x;
    if (f >= CC) return;
    int s = g_bstart[b], e = g_bstart[b + 1];
    float mx = 0.f, sm = 0.f;
    int n = s;
    // 4-way unrolled scan for MLP
    for (; n + 3 < e; n += 4) {
        float v0 = g_bufB[(size_t)(n + 0) * CC + f];
        float v1 = g_bufB[(size_t)(n + 1) * CC + f];
        float v2 = g_bufB[(size_t)(n + 2) * CC + f];
        float v3 = g_bufB[(size_t)(n + 3) * CC + f];
        mx = fmaxf(mx, fmaxf(fmaxf(v0, v1), fmaxf(v2, v3)));
        sm += (v0 + v1) + (v2 + v3);
    }
    for (; n < e; n++) {
        float v = g_bufB[(size_t)n * CC + f];
        mx = fmaxf(mx, v);
        sm += v;
    }
    g_g[b * 1560 + f] = mx;
    g_g[b * 1560 + 780 + f] = sm / fmaxf((float)(e - s), 1.f);
}

// ---------------- protein branches ----------------
__global__ void k_conv2(const int* __restrict__ t2, const float* __restrict__ emb,
                        const float* __restrict__ Wc2, const float* __restrict__ bc2)
{
    __shared__ float wag[26 * 256];
    int b = blockIdx.x;
    int tid = threadIdx.x;
    for (int v = 0; v < 26; v++) wag[v * 256 + tid] = 0.f;
    __syncthreads();
    int o = tid >> 3, k = tid & 7;
    const float* wcol = &Wc2[o * 8000 + k];
    const int* t2b = &t2[b * 1000];
    for (int i = 0; i < 1000; i++) {
        int v = t2b[i];
        wag[v * 256 + tid] += wcol[i * 8];
    }
    __syncthreads();
    for (int j = tid; j < 32 * 121; j += 256) {
        int oo = j / 121, l = j % 121;
        float acc = bc2[oo];
        for (int v = 0; v < 26; v++) {
            const float* wa = &wag[v * 256 + oo * 8];
            const float* er = &emb[v * 128 + l];
            #pragma unroll
            for (int kk = 0; kk < 8; kk++) acc += wa[kk] * er[kk];
        }
        g_xt2c[b * 3872 + j] = acc;
    }
}

__global__ void k_conv1(const float* __restrict__ t1, const float* __restrict__ Wc1,
                        const float* __restrict__ bc1)
{
    int b = blockIdx.x;
    int tid = threadIdx.x;
    int o = tid / 17, l = tid % 17;
    float acc = bc1[o];
    for (int i = 0; i < 20; i++) {
        const float* xr = &t1[b * 480 + i * 24 + l];
        const float* wr = &Wc1[o * 160 + i * 8];
        #pragma unroll
        for (int k = 0; k < 8; k++) acc += xr[k] * wr[k];
    }
    g_xt1c[b * 544 + tid] = acc;
}

// ---------------- launch ----------------
static inline dim3 gemm_grid(int M, int N) {
    return dim3((N + 63) / 64, (M + 63) / 64);
}

extern "C" void kernel_launch(void* const* d_in, const int* in_sizes, int n_in,
                              void* d_out, int out_size)
{
    const float* x       = (const float*)d_in[0];
    const int*   ei      = (const int*)  d_in[1];
    const int*   batch   = (const int*)  d_in[2];
    const float* target1 = (const float*)d_in[3];
    const int*   target2 = (const int*)  d_in[4];
    const float* W_gat   = (const float*)d_in[5];
    const float* att_src = (const float*)d_in[6];
    const float* att_dst = (const float*)d_in[7];
    const float* b_gat   = (const float*)d_in[8];
    const float* W_gcn   = (const float*)d_in[9];
    const float* b_gcn   = (const float*)d_in[10];
    const float* W_fcg1  = (const float*)d_in[11];
    const float* b_fcg1  = (const float*)d_in[12];
    const float* W_fcg2  = (const float*)d_in[13];
    const float* b_fcg2  = (const float*)d_in[14];
    const float* emb     = (const float*)d_in[15];
    const float* Wc2     = (const float*)d_in[16];
    const float* bc2     = (const float*)d_in[17];
    const float* W_fc2xt = (const float*)d_in[18];
    const float* b_fc2xt = (const float*)d_in[19];
    const float* Wc1     = (const float*)d_in[20];
    const float* bc1     = (const float*)d_in[21];
    const float* W_fc1xt = (const float*)d_in[22];
    const float* b_fc1xt = (const float*)d_in[23];
    const float* W_fc1   = (const float*)d_in[24];
    const float* b_fc1   = (const float*)d_in[25];
    const float* W_fc2   = (const float*)d_in[26];
    const float* b_fc2   = (const float*)d_in[27];
    const float* W_out   = (const float*)d_in[28];
    const float* b_out   = (const float*)d_in[29];
    float* out = (float*)d_out;

    int E0 = in_sizes[1] / 2;           // 150000
    int E  = E0 + NN;                   // + self loops

    // one-time host-side setup (no device allocations)
    static cudaStream_t s2 = nullptr, s3 = nullptr;
    static cudaEvent_t evFork = nullptr, evP1 = nullptr, evB2 = nullptr, evXt = nullptr;
    if (!s2) {
        cudaStreamCreateWithFlags(&s2, cudaStreamNonBlocking);
        cudaStreamCreateWithFlags(&s3, cudaStreamNonBlocking);
        cudaEventCreateWithFlags(&evFork, cudaEventDisableTiming);
        cudaEventCreateWithFlags(&evP1,   cudaEventDisableTiming);
        cudaEventCreateWithFlags(&evB2,   cudaEventDisableTiming);
        cudaEventCreateWithFlags(&evXt,   cudaEventDisableTiming);
        cudaFuncSetAttribute(wmma_gemm, cudaFuncAttributeMaxDynamicSharedMemorySize, WG_SMEM);
    }

    float *bufA, *pg, *pt1, *pxc, *pxt2c, *pxt1c, *pf1, *pf2, *pwproj, *pasd;
    __nv_bfloat16 *pAh, *pAl, *pBh1, *pBl1, *pBh2, *pBl2;
    cudaGetSymbolAddress((void**)&bufA,  g_bufA);
    cudaGetSymbolAddress((void**)&pAh,   g_Ah);
    cudaGetSymbolAddress((void**)&pAl,   g_Al);
    cudaGetSymbolAddress((void**)&pBh1,  g_Bh1);
    cudaGetSymbolAddress((void**)&pBl1,  g_Bl1);
    cudaGetSymbolAddress((void**)&pBh2,  g_Bh2);
    cudaGetSymbolAddress((void**)&pBl2,  g_Bl2);
    cudaGetSymbolAddress((void**)&pwproj, g_wproj);
    cudaGetSymbolAddress((void**)&pasd,  g_asd);
    cudaGetSymbolAddress((void**)&pg,    g_g);
    cudaGetSymbolAddress((void**)&pt1,   g_t1);
    cudaGetSymbolAddress((void**)&pxc,   g_xc);
    cudaGetSymbolAddress((void**)&pxt2c, g_xt2c);
    cudaGetSymbolAddress((void**)&pxt1c, g_xt1c);
    cudaGetSymbolAddress((void**)&pf1,   g_f1);
    cudaGetSymbolAddress((void**)&pf2,   g_f2);

    dim3 wg_grid(7, (NN + 127) / 128);   // N tiles x M tiles

    // ---- fork ----
    cudaEventRecord(evFork, 0);
    cudaStreamWaitEvent(s2, evFork, 0);
    cudaStreamWaitEvent(s3, evFork, 0);

    // ---- stream s2: attention stats (wproj -> asd), CSR chain, softmax pass1 ----
    k_wproj<<<(FD * 20 + 255) / 256, 256, 0, s2>>>(W_gat, att_src, att_dst);
    sgemm_kernel<false><<<gemm_grid(NN, 20), 256, 0, s2>>>(x, pwproj, nullptr, pasd, NN, 20, FD, 20);
    k_zero_deg<<<(NN + 255) / 256, 256, 0, s2>>>();
    k_count<<<(E + 255) / 256, 256, 0, s2>>>(ei, E0, E);
    k_scan1<<<NBLK, 1024, 0, s2>>>();
    k_scan2<<<1, 64, 0, s2>>>();
    k_scan3<<<(NN + 255) / 256, 256, 0, s2>>>();
    k_fillcsr<<<(E + 255) / 256, 256, 0, s2>>>(ei, E0, E);
    k_bstart<<<(NN + 255) / 256, 256, 0, s2>>>(batch);
    k_gat_pass1<<<(NN * 32 + 255) / 256, 256, 0, s2>>>();
    cudaEventRecord(evP1, s2);

    // ---- stream s3: GEMM2 B-conversion + protein branch ----
    {
        size_t nb2 = (size_t)KP2 * NP;
        k_convB<<<(int)((nb2 + 255) / 256), 256, 0, s3>>>(W_gcn, CC, CC, KP2, pBh2, pBl2);
        cudaEventRecord(evB2, s3);
        k_conv2<<<NB, 256, 0, s3>>>(target2, emb, Wc2, bc2);
        sgemm_kernel<false><<<gemm_grid(NB, 128), 256, 0, s3>>>(pxt2c, W_fc2xt, b_fc2xt, pxc + 256, NB, 128, 3872, 384);
        k_conv1<<<NB, 544, 0, s3>>>(target1, Wc1, bc1);
        sgemm_kernel<false><<<gemm_grid(NB, 128), 256, 0, s3>>>(pxt1c, W_fc1xt, b_fc1xt, pxc + 128, NB, 128, 544, 384);
        cudaEventRecord(evXt, s3);
    }

    // ---- default stream: GNN critical path ----
    // h = x @ W_gat (split-bf16 wmma)
    {
        size_t na = (size_t)NN * KP1;
        k_convA<false><<<(int)((na + 255) / 256), 256>>>(x, NN, FD, KP1, pAh, pAl);
        size_t nb = (size_t)KP1 * NP;
        k_convB<<<(int)((nb + 255) / 256), 256>>>(W_gat, FD, CC, KP1, pBh1, pBl1);
        wmma_gemm<<<wg_grid, 256, WG_SMEM>>>(pAh, pAl, pBh1, pBl1, bufA, NN, CC, KP1, CC);
    }

    // GAT pass2 (needs h + CSR + softmax stats -> join s2)
    cudaStreamWaitEvent(0, evP1, 0);
    k_gat_pass2<<<(NN * 32 + 255) / 256, 256>>>(b_gat);

    // hg = relu(gat_out) @ W_gcn (needs convB2 -> join s3's evB2)
    cudaStreamWaitEvent(0, evB2, 0);
    wmma_gemm<<<wg_grid, 256, WG_SMEM>>>(pAh, pAl, pBh2, pBl2, bufA, NN, CC, KP2, CC);

    // GCN gather + pooling
    k_gcn_gather<<<(NN * 32 + 255) / 256, 256>>>(b_gcn);
    k_pool2<<<dim3(4, NB), 256>>>();

    // graph MLP head
    sgemm_kernel<true ><<<gemm_grid(NB, 1500), 256>>>(pg,  W_fcg1, b_fcg1, pt1, NB, 1500, 1560, 1500);
    sgemm_kernel<false><<<gemm_grid(NB, 128),  256>>>(pt1, W_fcg2, b_fcg2, pxc + 0, NB, 128, 1500, 384);

    // final MLP (needs xt branches -> join s3)
    cudaStreamWaitEvent(0, evXt, 0);
    sgemm_kernel<true ><<<gemm_grid(NB, 1024), 256>>>(pxc, W_fc1, b_fc1, pf1, NB, 1024, 384, 1024);
    sgemm_kernel<true ><<<gemm_grid(NB, 512),  256>>>(pf1, W_fc2, b_fc2, pf2, NB, 512, 1024, 512);
    sgemm_kernel<false><<<gemm_grid(NB, 1),    256>>>(pf2, W_out, b_out, out, NB, 1, 512, 1);
}